// round 3
// baseline (speedup 1.0000x reference)
#include <cuda_runtime.h>
#include <cuda_bf16.h>

// RobustPrompt_I: graph prompt + edge pruning
//  in: x[N,128] f32, edge_index[2,E] i32, p_sim[1,128], p_deg[1,128], p_other[1,128]
//  out: x_new[N,128] f32  ++  keep[E] (0/1 as f32)

#define D        128
#define D4       32
#define NCAP     131072
#define ECAP     1048576
#define SIM_THR  0.2f
#define DEG_THR  3.0f
#define PT_THR   0.1f
#define EPSV     1e-8f

__device__ float  g_csum[NCAP];    // per-node sum of edge cosines
__device__ int    g_deg[NCAP];     // per-node degree
__device__ float  g_rinv[NCAP];    // 1/||x_i||
__device__ float4 g_A0[NCAP];      // (x·p_sim, x·p_deg, x·p_other, ||x||^2)
__device__ float  g_dot[ECAP];     // raw dot(x_r, x_c) per edge
__device__ float4 g_A[NCAP];       // (d0, d1, d2, 1/max(||x_new||,eps))
__device__ int    g_combo[NCAP];   // mask pattern idx: msim | (mdeg<<1); 0 => other
__device__ float  g_W[4][4];       // combo -> weight triple over prompts
__device__ float  g_GC[4][4];      // delta_a · delta_b LUT
__device__ float4 g_delta[4][D4];  // the 4 possible delta rows

// ---------- setup (1 warp): nz flags, Gram, weights, delta rows, LUTs ----------
__global__ void setup_kernel(const float* __restrict__ ps,
                             const float* __restrict__ pd,
                             const float* __restrict__ po) {
    int lane = threadIdx.x;
    unsigned full = 0xFFFFFFFFu;
    float4 P[3];
    P[0] = reinterpret_cast<const float4*>(ps)[lane];
    P[1] = reinterpret_cast<const float4*>(pd)[lane];
    P[2] = reinterpret_cast<const float4*>(po)[lane];

    int nz[3];
    #pragma unroll
    for (int k = 0; k < 3; k++) {
        bool z = (P[k].x != 0.f) & (P[k].y != 0.f) & (P[k].z != 0.f) & (P[k].w != 0.f);
        nz[k] = __all_sync(full, z);
    }
    float G[3][3];
    #pragma unroll
    for (int a = 0; a < 3; a++)
        #pragma unroll
        for (int b = 0; b < 3; b++) {
            float s = P[a].x * P[b].x + P[a].y * P[b].y + P[a].z * P[b].z + P[a].w * P[b].w;
            #pragma unroll
            for (int o = 16; o > 0; o >>= 1) s += __shfl_xor_sync(full, s, o);
            G[a][b] = s;   // every lane has the full value
        }
    // per-combo weights (every lane computes identically)
    float W[4][3];
    #pragma unroll
    for (int idx = 0; idx < 4; idx++) {
        int msim = idx & 1, mdeg = (idx >> 1) & 1, moth = (idx == 0);
        int plen = msim * nz[0] + mdeg * nz[1] + moth * nz[2];
        float inv = (plen > 0) ? (1.0f / (float)plen) : 0.0f;
        W[idx][0] = (float)msim * inv;
        W[idx][1] = (float)mdeg * inv;
        W[idx][2] = (float)moth * inv;
        // delta row for this combo
        float4 dl;
        dl.x = W[idx][0]*P[0].x + W[idx][1]*P[1].x + W[idx][2]*P[2].x;
        dl.y = W[idx][0]*P[0].y + W[idx][1]*P[1].y + W[idx][2]*P[2].y;
        dl.z = W[idx][0]*P[0].z + W[idx][1]*P[1].z + W[idx][2]*P[2].z;
        dl.w = W[idx][0]*P[0].w + W[idx][1]*P[1].w + W[idx][2]*P[2].w;
        g_delta[idx][lane] = dl;
    }
    if (lane == 0) {
        for (int idx = 0; idx < 4; idx++) {
            g_W[idx][0] = W[idx][0]; g_W[idx][1] = W[idx][1];
            g_W[idx][2] = W[idx][2]; g_W[idx][3] = 0.f;
        }
        for (int a = 0; a < 4; a++)
            for (int b = 0; b < 4; b++) {
                float s = 0.f;
                for (int k = 0; k < 3; k++)
                    for (int j = 0; j < 3; j++)
                        s += W[a][k] * G[k][j] * W[b][j];
                g_GC[a][b] = s;
            }
    }
}

// ---------- pass A (warp/node): ||x||^2, prompt dots, zero scratch ----------
__global__ void passA_kernel(const float* __restrict__ x,
                             const float* __restrict__ ps,
                             const float* __restrict__ pd,
                             const float* __restrict__ po, int n) {
    int w    = (blockIdx.x * blockDim.x + threadIdx.x) >> 5;
    int lane = threadIdx.x & 31;
    if (w >= n) return;
    float4 xv = reinterpret_cast<const float4*>(x)[(size_t)w * D4 + lane];
    float4 P0 = reinterpret_cast<const float4*>(ps)[lane];
    float4 P1 = reinterpret_cast<const float4*>(pd)[lane];
    float4 P2 = reinterpret_cast<const float4*>(po)[lane];

    float ss = xv.x*xv.x + xv.y*xv.y + xv.z*xv.z + xv.w*xv.w;
    float d0 = xv.x*P0.x + xv.y*P0.y + xv.z*P0.z + xv.w*P0.w;
    float d1 = xv.x*P1.x + xv.y*P1.y + xv.z*P1.z + xv.w*P1.w;
    float d2 = xv.x*P2.x + xv.y*P2.y + xv.z*P2.z + xv.w*P2.w;
    #pragma unroll
    for (int o = 16; o > 0; o >>= 1) {
        ss += __shfl_xor_sync(0xFFFFFFFFu, ss, o);
        d0 += __shfl_xor_sync(0xFFFFFFFFu, d0, o);
        d1 += __shfl_xor_sync(0xFFFFFFFFu, d1, o);
        d2 += __shfl_xor_sync(0xFFFFFFFFu, d2, o);
    }
    if (lane == 0) {
        g_rinv[w] = rsqrtf(ss);
        g_A0[w]   = make_float4(d0, d1, d2, ss);
        g_csum[w] = 0.f;
        g_deg[w]  = 0;
    }
}

// ---------- edge pass 1: raw dot + normalized scatter (8 lanes/edge) ----------
__global__ void edge1_kernel(const float* __restrict__ x,
                             const int* __restrict__ ei, int E) {
    int t   = blockIdx.x * blockDim.x + threadIdx.x;
    int e   = t >> 3;
    int sub = t & 7;
    if (e >= E) return;
    int r = __ldg(&ei[e]);
    int c = __ldg(&ei[E + e]);
    const float4* X = reinterpret_cast<const float4*>(x);
    const float4* Ar = X + (size_t)r * D4 + sub;
    const float4* Bc = X + (size_t)c * D4 + sub;
    float4 a0 = __ldg(Ar +  0), b0 = __ldg(Bc +  0);
    float4 a1 = __ldg(Ar +  8), b1 = __ldg(Bc +  8);
    float4 a2 = __ldg(Ar + 16), b2 = __ldg(Bc + 16);
    float4 a3 = __ldg(Ar + 24), b3 = __ldg(Bc + 24);
    float s = a0.x*b0.x + a0.y*b0.y + a0.z*b0.z + a0.w*b0.w;
    s += a1.x*b1.x + a1.y*b1.y + a1.z*b1.z + a1.w*b1.w;
    s += a2.x*b2.x + a2.y*b2.y + a2.z*b2.z + a2.w*b2.w;
    s += a3.x*b3.x + a3.y*b3.y + a3.z*b3.z + a3.w*b3.w;
    s += __shfl_xor_sync(0xFFFFFFFFu, s, 4);
    s += __shfl_xor_sync(0xFFFFFFFFu, s, 2);
    s += __shfl_xor_sync(0xFFFFFFFFu, s, 1);
    if (sub == 0) {
        g_dot[e] = s;
        float sn = s * g_rinv[r] * g_rinv[c];
        atomicAdd(&g_csum[c], sn);
        atomicAdd(&g_deg[c], 1);
    }
}

// ---------- node write (warp/node, NO reductions): x_new + per-node scalars ----------
__global__ void node_write_kernel(const float* __restrict__ x,
                                  float* __restrict__ out, int n) {
    int w    = (blockIdx.x * blockDim.x + threadIdx.x) >> 5;
    int lane = threadIdx.x & 31;
    if (w >= n) return;

    // broadcast loads (all lanes same address -> 1 transaction each)
    float cs  = g_csum[w];
    int   dg  = g_deg[w];
    float4 A0 = g_A0[w];          // (d0, d1, d2, ||x||^2)

    bool msim = (dg > 0) && ((cs / (float)dg) <= SIM_THR);
    bool mdeg = ((float)dg <= DEG_THR);
    int idx = (int)msim | ((int)mdeg << 1);   // 0 => other

    float4 xv = reinterpret_cast<const float4*>(x)[(size_t)w * D4 + lane];
    float4 dl = g_delta[idx][lane];           // L1-resident (2KB total)
    xv.x += dl.x; xv.y += dl.y; xv.z += dl.z; xv.w += dl.w;
    reinterpret_cast<float4*>(out)[(size_t)w * D4 + lane] = xv;

    if (lane == 0) {
        float xdd = g_W[idx][0]*A0.x + g_W[idx][1]*A0.y + g_W[idx][2]*A0.z;
        float nn2 = A0.w + 2.0f * xdd + g_GC[idx][idx];   // ||x_new||^2
        float rinv2 = 1.0f / fmaxf(sqrtf(fmaxf(nn2, 0.f)), EPSV);
        g_A[w] = make_float4(A0.x, A0.y, A0.z, rinv2);
        g_combo[w] = idx;
    }
}

// ---------- edge pass 2: decomposed cosine -> keep (thread/edge) ----------
__global__ void edge2_kernel(const int* __restrict__ ei,
                             float* __restrict__ keep, int E) {
    __shared__ float sW[4][4];
    __shared__ float sGC[4][4];
    if (threadIdx.x < 16) {
        sW[threadIdx.x >> 2][threadIdx.x & 3]  = g_W[threadIdx.x >> 2][threadIdx.x & 3];
        sGC[threadIdx.x >> 2][threadIdx.x & 3] = g_GC[threadIdx.x >> 2][threadIdx.x & 3];
    }
    __syncthreads();
    int e = blockIdx.x * blockDim.x + threadIdx.x;
    if (e >= E) return;
    int r = __ldg(&ei[e]);
    int c = __ldg(&ei[E + e]);
    float dot = g_dot[e];
    float4 Ar = g_A[r];
    float4 Ac = g_A[c];
    int cr = g_combo[r];
    int cc = g_combo[c];
    float num = dot
              + Ar.x * sW[cc][0] + Ar.y * sW[cc][1] + Ar.z * sW[cc][2]
              + Ac.x * sW[cr][0] + Ac.y * sW[cr][1] + Ac.z * sW[cr][2]
              + sGC[cr][cc];
    float cosv = num * Ar.w * Ac.w;
    keep[e] = (cosv >= PT_THR) ? 1.0f : 0.0f;
}

extern "C" void kernel_launch(void* const* d_in, const int* in_sizes, int n_in,
                              void* d_out, int out_size) {
    const float* x  = (const float*)d_in[0];
    const int*   ei = (const int*)d_in[1];
    const float* ps = (const float*)d_in[2];
    const float* pd = (const float*)d_in[3];
    const float* po = (const float*)d_in[4];
    float* out = (float*)d_out;

    int N = in_sizes[0] / D;
    int E = in_sizes[1] / 2;

    setup_kernel<<<1, 32>>>(ps, pd, po);
    passA_kernel<<<(N + 7) / 8, 256>>>(x, ps, pd, po, N);
    edge1_kernel<<<(E + 31) / 32, 256>>>(x, ei, E);
    node_write_kernel<<<(N + 7) / 8, 256>>>(x, out, N);
    if ((long long)out_size >= (long long)N * D + E) {
        edge2_kernel<<<(E + 255) / 256, 256>>>(ei, out + (size_t)N * D, E);
    }
}

// round 4
// speedup vs baseline: 1.0652x; 1.0652x over previous
#include <cuda_runtime.h>
#include <cuda_bf16.h>

// RobustPrompt_I: graph prompt + edge pruning
//  in: x[N,128] f32, edge_index[2,E] i32, p_sim[1,128], p_deg[1,128], p_other[1,128]
//  out: x_new[N,128] f32  ++  keep[E] (0/1 as f32)

#define D        128
#define D4       32
#define NCAP     131072
#define ECAP     1048576
#define SIM_THR  0.2f
#define DEG_THR  3.0f
#define PT_THR   0.1f
#define EPSV     1e-8f

__device__ float  g_csum[NCAP];    // per-node sum of edge cosines
__device__ int    g_deg[NCAP];     // per-node degree
__device__ float  g_rinv[NCAP];    // 1/||x_i||
__device__ float4 g_A0[NCAP];      // (x·p_sim, x·p_deg, x·p_other, ||x||^2)
__device__ float  g_dot[ECAP];     // raw dot(x_r, x_c) per edge
__device__ float4 g_A[NCAP];       // (d0, d1, d2, 1/max(||x_new||,eps))
__device__ int    g_combo[NCAP];   // mask pattern idx: msim | (mdeg<<1); 0 => other
__device__ float  g_W[4][4];       // combo -> weight triple over prompts
__device__ float  g_GC[4][4];      // delta_a · delta_b LUT
__device__ float4 g_delta[4][D4];  // the 4 possible delta rows

// ---------- setup (1 warp): nz flags, Gram, weights, delta rows, LUTs ----------
__global__ void setup_kernel(const float* __restrict__ ps,
                             const float* __restrict__ pd,
                             const float* __restrict__ po) {
    int lane = threadIdx.x;
    unsigned full = 0xFFFFFFFFu;
    float4 P[3];
    P[0] = reinterpret_cast<const float4*>(ps)[lane];
    P[1] = reinterpret_cast<const float4*>(pd)[lane];
    P[2] = reinterpret_cast<const float4*>(po)[lane];

    int nz[3];
    #pragma unroll
    for (int k = 0; k < 3; k++) {
        bool z = (P[k].x != 0.f) & (P[k].y != 0.f) & (P[k].z != 0.f) & (P[k].w != 0.f);
        nz[k] = __all_sync(full, z);
    }
    float G[3][3];
    #pragma unroll
    for (int a = 0; a < 3; a++)
        #pragma unroll
        for (int b = 0; b < 3; b++) {
            float s = P[a].x * P[b].x + P[a].y * P[b].y + P[a].z * P[b].z + P[a].w * P[b].w;
            #pragma unroll
            for (int o = 16; o > 0; o >>= 1) s += __shfl_xor_sync(full, s, o);
            G[a][b] = s;
        }
    float W[4][3];
    #pragma unroll
    for (int idx = 0; idx < 4; idx++) {
        int msim = idx & 1, mdeg = (idx >> 1) & 1, moth = (idx == 0);
        int plen = msim * nz[0] + mdeg * nz[1] + moth * nz[2];
        float inv = (plen > 0) ? (1.0f / (float)plen) : 0.0f;
        W[idx][0] = (float)msim * inv;
        W[idx][1] = (float)mdeg * inv;
        W[idx][2] = (float)moth * inv;
        float4 dl;
        dl.x = W[idx][0]*P[0].x + W[idx][1]*P[1].x + W[idx][2]*P[2].x;
        dl.y = W[idx][0]*P[0].y + W[idx][1]*P[1].y + W[idx][2]*P[2].y;
        dl.z = W[idx][0]*P[0].z + W[idx][1]*P[1].z + W[idx][2]*P[2].z;
        dl.w = W[idx][0]*P[0].w + W[idx][1]*P[1].w + W[idx][2]*P[2].w;
        g_delta[idx][lane] = dl;
    }
    if (lane == 0) {
        for (int idx = 0; idx < 4; idx++) {
            g_W[idx][0] = W[idx][0]; g_W[idx][1] = W[idx][1];
            g_W[idx][2] = W[idx][2]; g_W[idx][3] = 0.f;
        }
        for (int a = 0; a < 4; a++)
            for (int b = 0; b < 4; b++) {
                float s = 0.f;
                for (int k = 0; k < 3; k++)
                    for (int j = 0; j < 3; j++)
                        s += W[a][k] * G[k][j] * W[b][j];
                g_GC[a][b] = s;
            }
    }
}

// ---------- pass A (warp/node): ||x||^2, prompt dots, zero scratch ----------
__global__ void passA_kernel(const float* __restrict__ x,
                             const float* __restrict__ ps,
                             const float* __restrict__ pd,
                             const float* __restrict__ po, int n) {
    int w    = (blockIdx.x * blockDim.x + threadIdx.x) >> 5;
    int lane = threadIdx.x & 31;
    if (w >= n) return;
    float4 xv = reinterpret_cast<const float4*>(x)[(size_t)w * D4 + lane];
    float4 P0 = reinterpret_cast<const float4*>(ps)[lane];
    float4 P1 = reinterpret_cast<const float4*>(pd)[lane];
    float4 P2 = reinterpret_cast<const float4*>(po)[lane];

    float ss = xv.x*xv.x + xv.y*xv.y + xv.z*xv.z + xv.w*xv.w;
    float d0 = xv.x*P0.x + xv.y*P0.y + xv.z*P0.z + xv.w*P0.w;
    float d1 = xv.x*P1.x + xv.y*P1.y + xv.z*P1.z + xv.w*P1.w;
    float d2 = xv.x*P2.x + xv.y*P2.y + xv.z*P2.z + xv.w*P2.w;
    #pragma unroll
    for (int o = 16; o > 0; o >>= 1) {
        ss += __shfl_xor_sync(0xFFFFFFFFu, ss, o);
        d0 += __shfl_xor_sync(0xFFFFFFFFu, d0, o);
        d1 += __shfl_xor_sync(0xFFFFFFFFu, d1, o);
        d2 += __shfl_xor_sync(0xFFFFFFFFu, d2, o);
    }
    if (lane == 0) {
        g_rinv[w] = rsqrtf(ss);
        g_A0[w]   = make_float4(d0, d1, d2, ss);
        g_csum[w] = 0.f;
        g_deg[w]  = 0;
    }
}

// ---------- edge pass 1: 2 edges per 8-lane group, 16 loads in flight ----------
__global__ void edge1_kernel(const float* __restrict__ x,
                             const int* __restrict__ ei, int E) {
    int t   = blockIdx.x * blockDim.x + threadIdx.x;
    int g   = t >> 3;
    int sub = t & 7;
    int e0  = g * 2;
    int e1  = e0 + 1;
    if (e0 >= E) return;
    bool has1 = (e1 < E);
    const float4* X = reinterpret_cast<const float4*>(x);

    int r0 = __ldg(&ei[e0]);
    int c0 = __ldg(&ei[E + e0]);
    int r1 = has1 ? __ldg(&ei[e1]) : r0;
    int c1 = has1 ? __ldg(&ei[E + e1]) : c0;

    const float4* Ar0 = X + (size_t)r0 * D4 + sub;
    const float4* Bc0 = X + (size_t)c0 * D4 + sub;
    const float4* Ar1 = X + (size_t)r1 * D4 + sub;
    const float4* Bc1 = X + (size_t)c1 * D4 + sub;

    float4 a0[4], b0[4], a1[4], b1[4];
    #pragma unroll
    for (int k = 0; k < 4; k++) a0[k] = __ldg(Ar0 + 8 * k);
    #pragma unroll
    for (int k = 0; k < 4; k++) b0[k] = __ldg(Bc0 + 8 * k);
    #pragma unroll
    for (int k = 0; k < 4; k++) a1[k] = __ldg(Ar1 + 8 * k);
    #pragma unroll
    for (int k = 0; k < 4; k++) b1[k] = __ldg(Bc1 + 8 * k);

    float s0 = 0.f, s1 = 0.f;
    #pragma unroll
    for (int k = 0; k < 4; k++) {
        s0 += a0[k].x*b0[k].x + a0[k].y*b0[k].y + a0[k].z*b0[k].z + a0[k].w*b0[k].w;
        s1 += a1[k].x*b1[k].x + a1[k].y*b1[k].y + a1[k].z*b1[k].z + a1[k].w*b1[k].w;
    }
    #pragma unroll
    for (int o = 4; o > 0; o >>= 1) {
        s0 += __shfl_xor_sync(0xFFFFFFFFu, s0, o);
        s1 += __shfl_xor_sync(0xFFFFFFFFu, s1, o);
    }
    if (sub == 0) {
        g_dot[e0] = s0;
        float sn0 = s0 * g_rinv[r0] * g_rinv[c0];
        atomicAdd(&g_csum[c0], sn0);
        atomicAdd(&g_deg[c0], 1);
        if (has1) {
            g_dot[e1] = s1;
            float sn1 = s1 * g_rinv[r1] * g_rinv[c1];
            atomicAdd(&g_csum[c1], sn1);
            atomicAdd(&g_deg[c1], 1);
        }
    }
}

// ---------- combo (thread/node): masks, ||x_new|| via algebra ----------
__global__ void combo_kernel(int n) {
    int w = blockIdx.x * blockDim.x + threadIdx.x;
    if (w >= n) return;
    float cs  = g_csum[w];
    int   dg  = g_deg[w];
    float4 A0 = g_A0[w];
    bool msim = (dg > 0) && ((cs / (float)dg) <= SIM_THR);
    bool mdeg = ((float)dg <= DEG_THR);
    int idx = (int)msim | ((int)mdeg << 1);
    float xdd = g_W[idx][0]*A0.x + g_W[idx][1]*A0.y + g_W[idx][2]*A0.z;
    float nn2 = A0.w + 2.0f * xdd + g_GC[idx][idx];
    float rinv2 = 1.0f / fmaxf(sqrtf(fmaxf(nn2, 0.f)), EPSV);
    g_A[w] = make_float4(A0.x, A0.y, A0.z, rinv2);
    g_combo[w] = idx;
}

// ---------- fused finish: node write (block-specialized) + edge2 ----------
__global__ void finish_kernel(const float* __restrict__ x,
                              const int* __restrict__ ei,
                              float* __restrict__ out,
                              float* __restrict__ keep,
                              int n, int E, int NBn) {
    if ((int)blockIdx.x < NBn) {
        // ---- node write: 16 nodes/block, 16 lanes/node, 2 float4/thread ----
        int tid  = threadIdx.x;
        int node = blockIdx.x * 16 + (tid >> 4);
        if (node >= n) return;
        int j = tid & 15;
        int idx = g_combo[node];
        const float4* Xr = reinterpret_cast<const float4*>(x) + (size_t)node * D4;
        float4 xv0 = __ldg(Xr + j);
        float4 xv1 = __ldg(Xr + j + 16);
        float4 dl0 = g_delta[idx][j];
        float4 dl1 = g_delta[idx][j + 16];
        xv0.x += dl0.x; xv0.y += dl0.y; xv0.z += dl0.z; xv0.w += dl0.w;
        xv1.x += dl1.x; xv1.y += dl1.y; xv1.z += dl1.z; xv1.w += dl1.w;
        float4* Or = reinterpret_cast<float4*>(out) + (size_t)node * D4;
        Or[j]      = xv0;
        Or[j + 16] = xv1;
    } else {
        // ---- edge2: decomposed cosine -> keep (thread/edge) ----
        __shared__ float sW[4][4];
        __shared__ float sGC[4][4];
        if (threadIdx.x < 16) {
            sW[threadIdx.x >> 2][threadIdx.x & 3]  = g_W[threadIdx.x >> 2][threadIdx.x & 3];
            sGC[threadIdx.x >> 2][threadIdx.x & 3] = g_GC[threadIdx.x >> 2][threadIdx.x & 3];
        }
        __syncthreads();
        int e = (blockIdx.x - NBn) * blockDim.x + threadIdx.x;
        if (e >= E) return;
        int r = __ldg(&ei[e]);
        int c = __ldg(&ei[E + e]);
        float dot = g_dot[e];
        float4 Ar = g_A[r];
        float4 Ac = g_A[c];
        int cr = g_combo[r];
        int cc = g_combo[c];
        float num = dot
                  + Ar.x * sW[cc][0] + Ar.y * sW[cc][1] + Ar.z * sW[cc][2]
                  + Ac.x * sW[cr][0] + Ac.y * sW[cr][1] + Ac.z * sW[cr][2]
                  + sGC[cr][cc];
        float cosv = num * Ar.w * Ac.w;
        keep[e] = (cosv >= PT_THR) ? 1.0f : 0.0f;
    }
}

extern "C" void kernel_launch(void* const* d_in, const int* in_sizes, int n_in,
                              void* d_out, int out_size) {
    const float* x  = (const float*)d_in[0];
    const int*   ei = (const int*)d_in[1];
    const float* ps = (const float*)d_in[2];
    const float* pd = (const float*)d_in[3];
    const float* po = (const float*)d_in[4];
    float* out = (float*)d_out;

    int N = in_sizes[0] / D;
    int E = in_sizes[1] / 2;

    setup_kernel<<<1, 32>>>(ps, pd, po);
    passA_kernel<<<(N + 7) / 8, 256>>>(x, ps, pd, po, N);
    {
        int groups = (E + 1) / 2;                 // 8 lanes per 2 edges
        int threads = groups * 8;
        edge1_kernel<<<(threads + 255) / 256, 256>>>(x, ei, E);
    }
    combo_kernel<<<(N + 255) / 256, 256>>>(N);

    int NBn = (N + 15) / 16;
    bool do_keep = ((long long)out_size >= (long long)N * D + E);
    int NBe = do_keep ? (E + 255) / 256 : 0;
    float* keep = out + (size_t)N * D;
    finish_kernel<<<NBn + NBe, 256>>>(x, ei, out, keep, N, E, NBn);
}